// round 3
// baseline (speedup 1.0000x reference)
#include <cuda_runtime.h>
#include <cuda_bf16.h>
#include <math.h>

// Problem constants (fixed by the bench)
#define BATCH 8
#define CIN   64
#define COUT  64
#define NPT   2048
#define DTOT  192           // 3*Cin feature dim for kNN
#define KNN   11            // k+1
#define NPAIR (BATCH*NPT)   // 16384 points total
#define NEDGE (BATCH*NPT*KNN)
#define TCAND 16            // candidates kept per row before exact refine

#define VN_EPS 1e-6f
#define BN_EPS 1e-5f

// ---------------- scratch (device globals; no cudaMalloc allowed) ----------------
__device__ float  g_pdist[(size_t)BATCH * NPT * NPT];   // 134 MB
__device__ float  g_xt[(size_t)NPAIR * DTOT];           // transposed x: [bm][d]
__device__ double g_xx64[NPAIR];
__device__ float  g_xx[NPAIR];
__device__ int    g_cand[(size_t)NPAIR * TCAND];
__device__ int    g_idx[NEDGE];
__device__ float  g_yf[(size_t)NPAIR * DTOT];           // [bm][o*3+d]
__device__ float  g_yd[(size_t)NPAIR * DTOT];
__device__ float  g_nrm[(size_t)NPAIR * COUT];          // [bm][o]
__device__ float  g_dfd[(size_t)NPAIR * COUT];
__device__ float  g_dsq[(size_t)NPAIR * COUT];
__device__ float  g_v[(size_t)NPAIR * DTOT];            // per-point output vectors
__device__ int    g_cnt[NPAIR];
__device__ float  g_chA[COUT];
__device__ float  g_chB[COUT];

// ---------------- f32x2 packed helpers ----------------
__device__ __forceinline__ unsigned long long pk2(float lo, float hi) {
    unsigned long long r;
    asm("mov.b64 %0, {%1, %2};" : "=l"(r) : "f"(lo), "f"(hi));
    return r;
}
__device__ __forceinline__ unsigned long long ffma2(unsigned long long a, unsigned long long b, unsigned long long c) {
    unsigned long long d;
    asm("fma.rn.f32x2 %0, %1, %2, %3;" : "=l"(d) : "l"(a), "l"(b), "l"(c));
    return d;
}
__device__ __forceinline__ float2 upk2(unsigned long long v) {
    float2 r;
    asm("mov.b64 {%0, %1}, %2;" : "=f"(r.x), "=f"(r.y) : "l"(v));
    return r;
}

// ---------------- 0: transpose x -> g_xt [bm][d] (coalesced column access) ----------------
__global__ void xt_kernel(const float* __restrict__ x) {
    __shared__ float t[32][33];
    int b  = blockIdx.z;
    int d0 = blockIdx.y * 32;
    int n0 = blockIdx.x * 32;
    const float* X = x + (size_t)b * DTOT * NPT;
    t[threadIdx.y][threadIdx.x] = X[(size_t)(d0 + threadIdx.y) * NPT + n0 + threadIdx.x];
    __syncthreads();
    g_xt[((size_t)(b << 11) + n0 + threadIdx.y) * DTOT + d0 + threadIdx.x] = t[threadIdx.x][threadIdx.y];
}

// ---------------- 1: xx in fp64 (exact) + fp32 copy for the approx GEMM ----------------
__global__ void xx64_kernel() {
    int p = blockIdx.x * blockDim.x + threadIdx.x;      // 16384 points
    const float* r = g_xt + (size_t)p * DTOT;
    double s = 0.0;
    #pragma unroll 8
    for (int d = 0; d < DTOT; d++) { double v = (double)r[d]; s += v * v; }
    g_xx64[p] = s;
    g_xx[p] = (float)s;
}

// ---------------- 2: approx pdist = 2*X^T X - xx_n - xx_m  (per batch, fp32) ----------------
#define BM 128
#define BN 128
#define BK 16
__global__ __launch_bounds__(256, 2) void knn_gemm(const float* __restrict__ x) {
    int b  = blockIdx.z;
    int n0 = blockIdx.y * BM;
    int m0 = blockIdx.x * BN;
    const float* X = x + (size_t)b * DTOT * NPT;

    __shared__ float As[BK][BM];
    __shared__ float Bs[BK][BN];

    int tid = threadIdx.x;
    int tx = tid & 15;
    int ty = tid >> 4;

    unsigned long long acc[8][4];
    #pragma unroll
    for (int i = 0; i < 8; i++)
        #pragma unroll
        for (int j = 0; j < 4; j++) acc[i][j] = 0ull;

    for (int kt = 0; kt < DTOT; kt += BK) {
        #pragma unroll
        for (int r = 0; r < 2; r++) {
            int i  = tid + r * 256;
            int kk = i >> 5;
            int c4 = i & 31;
            float4 va = *(const float4*)&X[(size_t)(kt + kk) * NPT + n0 + c4 * 4];
            *(float4*)&As[kk][c4 * 4] = va;
            float4 vb = *(const float4*)&X[(size_t)(kt + kk) * NPT + m0 + c4 * 4];
            *(float4*)&Bs[kk][c4 * 4] = vb;
        }
        __syncthreads();
        #pragma unroll
        for (int kk = 0; kk < BK; kk++) {
            float a[8];
            *(float4*)(a)     = *(const float4*)&As[kk][ty * 8];
            *(float4*)(a + 4) = *(const float4*)&As[kk][ty * 8 + 4];
            unsigned long long bq[4];
            const unsigned long long* bp = (const unsigned long long*)&Bs[kk][tx * 8];
            bq[0] = bp[0]; bq[1] = bp[1]; bq[2] = bp[2]; bq[3] = bp[3];
            #pragma unroll
            for (int i = 0; i < 8; i++) {
                unsigned long long ad = pk2(a[i], a[i]);
                #pragma unroll
                for (int j = 0; j < 4; j++) acc[i][j] = ffma2(ad, bq[j], acc[i][j]);
            }
        }
        __syncthreads();
    }

    float xm[8];
    #pragma unroll
    for (int j = 0; j < 8; j++) xm[j] = g_xx[b * NPT + m0 + tx * 8 + j];

    float* out = g_pdist + ((size_t)b * NPT + n0) * NPT + m0;
    #pragma unroll
    for (int i = 0; i < 8; i++) {
        float xn = g_xx[b * NPT + n0 + ty * 8 + i];
        float r[8];
        #pragma unroll
        for (int j = 0; j < 4; j++) {
            float2 u = upk2(acc[i][j]);
            r[2 * j]     = 2.f * u.x - xn - xm[2 * j];
            r[2 * j + 1] = 2.f * u.y - xn - xm[2 * j + 1];
        }
        float* op = out + (size_t)(ty * 8 + i) * NPT + tx * 8;
        *(float4*)(op)     = make_float4(r[0], r[1], r[2], r[3]);
        *(float4*)(op + 4) = make_float4(r[4], r[5], r[6], r[7]);
    }
}

// ---------------- 3: approx top-TCAND per row (warp per row) ----------------
__global__ void cand_kernel() {
    int gwarp = (blockIdx.x * blockDim.x + threadIdx.x) >> 5;   // row id [0,16384)
    int lane  = threadIdx.x & 31;
    int wl    = threadIdx.x >> 5;

    __shared__ float sv[8][32 * TCAND];
    __shared__ int   si[8][32 * TCAND];

    const float* row = g_pdist + (size_t)gwarp * NPT;
    float tv[TCAND]; int ti[TCAND];
    #pragma unroll
    for (int j = 0; j < TCAND; j++) { tv[j] = -INFINITY; ti[j] = 0; }

    for (int i = 0; i < NPT / 32; i++) {
        int m = lane + (i << 5);
        float vv = row[m];
        if (vv > tv[TCAND - 1]) {
            float cv = vv; int ci = m;
            #pragma unroll
            for (int j = 0; j < TCAND; j++) {
                if (cv > tv[j]) {
                    float t = tv[j]; tv[j] = cv; cv = t;
                    int q = ti[j]; ti[j] = ci; ci = q;
                }
            }
        }
    }
    #pragma unroll
    for (int j = 0; j < TCAND; j++) {
        sv[wl][lane * TCAND + j] = tv[j];
        si[wl][lane * TCAND + j] = ti[j];
    }
    __syncwarp();

    int* out = g_cand + (size_t)gwarp * TCAND;
    for (int r = 0; r < TCAND; r++) {
        float bv = -INFINITY; int bs = 0;
        #pragma unroll
        for (int t = 0; t < TCAND; t++) {
            int s = lane * TCAND + t;
            float vv = sv[wl][s];
            if (vv > bv) { bv = vv; bs = s; }
        }
        #pragma unroll
        for (int off = 16; off; off >>= 1) {
            float ov = __shfl_down_sync(0xffffffff, bv, off);
            int   os = __shfl_down_sync(0xffffffff, bs, off);
            if (ov > bv) { bv = ov; bs = os; }
        }
        bs = __shfl_sync(0xffffffff, bs, 0);
        if (lane == 0) { out[r] = si[wl][bs]; sv[wl][bs] = -INFINITY; }
        __syncwarp();
    }
}

// ---------------- 4: exact fp64 refine of candidates -> final top-KNN ----------------
__global__ __launch_bounds__(256) void refine_kernel() {
    int row  = (blockIdx.x * blockDim.x + threadIdx.x) >> 5;  // [0,16384)
    int lane = threadIdx.x & 31;
    int wl   = threadIdx.x >> 5;
    int b    = row >> 11;

    __shared__ float s_val[8][TCAND];
    __shared__ int   s_id[8][TCAND];

    float xn[6];
    #pragma unroll
    for (int u = 0; u < 6; u++) xn[u] = g_xt[(size_t)row * DTOT + lane + 32 * u];
    float xxn = (float)g_xx64[row];

    for (int j = 0; j < TCAND; j++) {
        int m = g_cand[(size_t)row * TCAND + j];
        const float* xm = g_xt + ((size_t)(b << 11) + m) * DTOT;
        double acc = 0.0;
        #pragma unroll
        for (int u = 0; u < 6; u++) acc += (double)xn[u] * (double)xm[lane + 32 * u];
        #pragma unroll
        for (int off = 16; off; off >>= 1) acc += __shfl_down_sync(0xffffffff, acc, off);
        if (lane == 0) {
            // emulate reference's fp32 expression structure for tie alignment:
            // pdist = (2*inner_f32 - xx_n_f32) - xx_m_f32
            float innerf = (float)acc;
            float pf = 2.0f * innerf;
            pf = pf - xxn;
            pf = pf - (float)g_xx64[(size_t)(b << 11) + m];
            s_val[wl][j] = pf;
            s_id[wl][j]  = m;
        }
    }
    __syncwarp();

    if (lane == 0) {
        int* out = g_idx + (size_t)row * KNN;
        for (int r = 0; r < KNN; r++) {
            float bv = -INFINITY; int bi = 0x7fffffff; int bs = 0;
            #pragma unroll
            for (int t = 0; t < TCAND; t++) {
                float v = s_val[wl][t]; int id = s_id[wl][t];
                // jax top_k tie rule: larger value first, lower index on ties
                if (v > bv || (v == bv && id < bi)) { bv = v; bi = id; bs = t; }
            }
            out[r] = bi;
            s_val[wl][bs] = -INFINITY;
        }
    }
}

// ---------------- 5: y_feat / y_dir  [bm][od] ----------------
__global__ void feat_kernel(const float* __restrict__ x,
                            const float* __restrict__ Wf,
                            const float* __restrict__ Wd) {
    __shared__ float wfs[64][64];   // [c][o]
    __shared__ float wds[64][64];
    __shared__ float xs[DTOT][16];

    int b = blockIdx.y;
    int n0 = blockIdx.x * 16;
    int tid = threadIdx.x;          // 192

    for (int i = tid; i < 4096; i += 192) {
        int o = i >> 6, c = i & 63;
        wfs[c][o] = Wf[i];
        wds[c][o] = Wd[i];
    }
    const float* X = x + (size_t)b * DTOT * NPT;
    for (int i = tid; i < DTOT * 16; i += 192) {
        int c3 = i >> 4, n = i & 15;
        xs[c3][n] = X[(size_t)c3 * NPT + n0 + n];
    }
    __syncthreads();

    int o = tid / 3;
    int d = tid - 3 * o;

    float af[16], ad_[16];
    #pragma unroll
    for (int n = 0; n < 16; n++) { af[n] = 0.f; ad_[n] = 0.f; }

    for (int c = 0; c < 64; c++) {
        float wf = wfs[c][o], wd = wds[c][o];
        #pragma unroll
        for (int n = 0; n < 16; n++) {
            float xv = xs[c * 3 + d][n];
            af[n]  = fmaf(wf, xv, af[n]);
            ad_[n] = fmaf(wd, xv, ad_[n]);
        }
    }
    #pragma unroll
    for (int n = 0; n < 16; n++) {
        size_t base = ((size_t)b * NPT + n0 + n) * DTOT + tid;
        g_yf[base] = af[n];
        g_yd[base] = ad_[n];
    }
}

// ---------------- 6: per-point norm / f·d / |d|^2 ----------------
__global__ void pstat_kernel() {
    int t = blockIdx.x * blockDim.x + threadIdx.x;  // 16384*64
    int bm = t >> 6;
    int o  = t & 63;
    const float* f = g_yf + (size_t)bm * DTOT + o * 3;
    const float* g = g_yd + (size_t)bm * DTOT + o * 3;
    float f0 = f[0], f1 = f[1], f2 = f[2];
    float g0 = g[0], g1 = g[1], g2 = g[2];
    g_nrm[t] = sqrtf(f0 * f0 + f1 * f1 + f2 * f2);
    g_dfd[t] = f0 * g0 + f1 * g1 + f2 * g2;
    g_dsq[t] = g0 * g0 + g1 * g1 + g2 * g2;
}

// ---------------- 7: neighbor counts ----------------
__global__ void zero_cnt() {
    int t = blockIdx.x * blockDim.x + threadIdx.x;
    if (t < NPAIR) g_cnt[t] = 0;
}
__global__ void count_kernel() {
    int t = blockIdx.x * blockDim.x + threadIdx.x;  // NEDGE = 180224
    if (t < NEDGE) {
        int b = t / (NPT * KNN);
        atomicAdd(&g_cnt[b * NPT + g_idx[t]], 1);
    }
}

// ---------------- 8: BN stats (count-weighted, exact) ----------------
__global__ void bnstat_kernel(const float* __restrict__ gamma, const float* __restrict__ beta) {
    int o = blockIdx.x;
    int tid = threadIdx.x;  // 256
    double s1 = 0.0, s2 = 0.0;
    for (int bm = tid; bm < NPAIR; bm += 256) {
        float v = g_nrm[(size_t)bm * COUT + o];
        double c = (double)g_cnt[bm];
        s1 += c * v;
        s2 += c * (double)v * (double)v;
    }
    __shared__ double r1[256], r2[256];
    r1[tid] = s1; r2[tid] = s2;
    __syncthreads();
    for (int s = 128; s; s >>= 1) {
        if (tid < s) { r1[tid] += r1[tid + s]; r2[tid] += r2[tid + s]; }
        __syncthreads();
    }
    if (tid == 0) {
        const double cnt = (double)NEDGE;
        double mean = r1[0] / cnt;
        double var  = r2[0] / cnt - mean * mean;
        double a = (double)gamma[o] / sqrt(var + (double)BN_EPS);
        g_chA[o] = (float)a;
        g_chB[o] = (float)((double)beta[o] - mean * a);
    }
}

// ---------------- 9: per-point output vectors v ----------------
__global__ void v_kernel() {
    int bm = blockIdx.x;
    int od = threadIdx.x;       // 192
    int o = od / 3;
    size_t t = (size_t)bm * DTOT + od;
    size_t s = (size_t)bm * COUT + o;
    float n    = g_nrm[s];
    float scale = g_chA[o] + g_chB[o] / n;     // norm_bn / norm
    float dot  = scale * g_dfd[s];
    float pv   = scale * g_yf[t];
    float outv = pv;
    if (dot < 0.f) outv = pv - dot / (g_dsq[s] + VN_EPS) * g_yd[t];
    g_v[t] = outv;
}

// ---------------- 10: gather-mean to output ----------------
__global__ void gather_kernel(float* __restrict__ out) {
    __shared__ int sidx[16 * KNN];
    int b  = blockIdx.y;
    int n0 = blockIdx.x * 16;
    int tid = threadIdx.x;      // 192
    if (tid < 16 * KNN) sidx[tid] = g_idx[((size_t)b * NPT + n0) * KNN + tid];
    __syncthreads();

    const float* vb = g_v + (size_t)b * NPT * DTOT;
    float res[16];
    #pragma unroll
    for (int n = 0; n < 16; n++) {
        float acc = 0.f;
        #pragma unroll
        for (int k = 0; k < KNN; k++) {
            int m = sidx[n * KNN + k];
            acc += vb[(size_t)m * DTOT + tid];
        }
        res[n] = acc * (1.0f / (float)KNN);
    }
    float* ob = out + ((size_t)b * DTOT + tid) * NPT + n0;
    *(float4*)(ob)      = make_float4(res[0],  res[1],  res[2],  res[3]);
    *(float4*)(ob + 4)  = make_float4(res[4],  res[5],  res[6],  res[7]);
    *(float4*)(ob + 8)  = make_float4(res[8],  res[9],  res[10], res[11]);
    *(float4*)(ob + 12) = make_float4(res[12], res[13], res[14], res[15]);
}

// ---------------- launch ----------------
extern "C" void kernel_launch(void* const* d_in, const int* in_sizes, int n_in,
                              void* d_out, int out_size) {
    const float* x     = (const float*)d_in[0];
    const float* Wf    = (const float*)d_in[1];
    const float* Wd    = (const float*)d_in[2];
    const float* gamma = (const float*)d_in[3];
    const float* beta  = (const float*)d_in[4];
    float* out = (float*)d_out;

    xt_kernel<<<dim3(NPT / 32, DTOT / 32, BATCH), dim3(32, 32)>>>(x);
    xx64_kernel<<<NPAIR / 256, 256>>>();
    knn_gemm<<<dim3(NPT / BN, NPT / BM, BATCH), 256>>>(x);
    cand_kernel<<<NPAIR / 8, 256>>>();
    refine_kernel<<<NPAIR / 8, 256>>>();
    feat_kernel<<<dim3(NPT / 16, BATCH), 192>>>(x, Wf, Wd);
    pstat_kernel<<<(NPAIR * COUT) / 256, 256>>>();
    zero_cnt<<<NPAIR / 256, 256>>>();
    count_kernel<<<(NEDGE + 255) / 256, 256>>>();
    bnstat_kernel<<<COUT, 256>>>(gamma, beta);
    v_kernel<<<NPAIR, DTOT>>>();
    gather_kernel<<<dim3(NPT / 16, BATCH), DTOT>>>(out);
}

// round 4
// speedup vs baseline: 1.7263x; 1.7263x over previous
#include <cuda_runtime.h>
#include <cuda_bf16.h>
#include <mma.h>
#include <math.h>

using namespace nvcuda;

// Problem constants (fixed by the bench)
#define BATCH 8
#define CIN   64
#define COUT  64
#define NPT   2048
#define DTOT  192           // 3*Cin feature dim for kNN
#define KNN   11            // k+1
#define NPAIR (BATCH*NPT)   // 16384 points total
#define NEDGE (BATCH*NPT*KNN)
#define TCAND 16            // candidates kept per row before exact refine

#define VN_EPS 1e-6f
#define BN_EPS 1e-5f

// ---------------- scratch (device globals; no cudaMalloc allowed) ----------------
__device__ float          g_pdist[(size_t)BATCH * NPT * NPT];   // 134 MB (rank scores)
__device__ float          g_xt[(size_t)NPAIR * DTOT];           // transposed x: [bm][d]
__device__ __nv_bfloat16  g_hi[(size_t)NPAIR * DTOT];           // bf16 hi part of xt
__device__ __nv_bfloat16  g_lo[(size_t)NPAIR * DTOT];           // bf16 lo part
__device__ double         g_xx64[NPAIR];
__device__ __nv_bfloat16  g_hx[NPAIR];                          // bf16 hi of -0.5*xx
__device__ __nv_bfloat16  g_lx[NPAIR];                          // bf16 lo of -0.5*xx
__device__ int            g_cand[(size_t)NPAIR * TCAND];
__device__ int            g_idx[NEDGE];
__device__ float          g_yf[(size_t)NPAIR * DTOT];           // [bm][o*3+d]
__device__ float          g_yd[(size_t)NPAIR * DTOT];
__device__ float          g_nrm[(size_t)NPAIR * COUT];          // [bm][o]
__device__ float          g_dfd[(size_t)NPAIR * COUT];
__device__ float          g_dsq[(size_t)NPAIR * COUT];
__device__ float          g_v[(size_t)NPAIR * DTOT];            // per-point output vectors
__device__ int            g_cnt[NPAIR];
__device__ float          g_chA[COUT];
__device__ float          g_chB[COUT];

// ---------------- 0: transpose x -> g_xt [bm][d]; emit bf16 hi/lo split ----------------
__global__ void xt_kernel(const float* __restrict__ x) {
    __shared__ float t[32][33];
    int b  = blockIdx.z;
    int d0 = blockIdx.y * 32;
    int n0 = blockIdx.x * 32;
    const float* X = x + (size_t)b * DTOT * NPT;
    t[threadIdx.y][threadIdx.x] = X[(size_t)(d0 + threadIdx.y) * NPT + n0 + threadIdx.x];
    __syncthreads();
    float v = t[threadIdx.x][threadIdx.y];
    size_t o = ((size_t)(b << 11) + n0 + threadIdx.y) * DTOT + d0 + threadIdx.x;
    g_xt[o] = v;
    __nv_bfloat16 h = __float2bfloat16(v);
    g_hi[o] = h;
    g_lo[o] = __float2bfloat16(v - __bfloat162float(h));
}

// ---------------- 1: xx in fp64 (exact) + bf16 hi/lo of -0.5*xx ----------------
__global__ void xx64_kernel() {
    int p = blockIdx.x * blockDim.x + threadIdx.x;      // 16384 points
    const float* r = g_xt + (size_t)p * DTOT;
    double s = 0.0;
    #pragma unroll 8
    for (int d = 0; d < DTOT; d++) { double v = (double)r[d]; s += v * v; }
    g_xx64[p] = s;
    float m05 = (float)(-0.5 * s);
    __nv_bfloat16 hx = __float2bfloat16(m05);
    g_hx[p] = hx;
    g_lx[p] = __float2bfloat16(m05 - __bfloat162float(hx));
}

// ---------------- 2: tensor-core rank-score GEMM ----------------
// score[n][m] = sum_d x_n.x_m  - 0.5*xx_m  (per-row-monotone transform of pdist)
// computed as bf16 3-term split: [hi,hi,lo] . [hi,lo,hi]  + aug cols [1,1].[hx,lx]
#define SMLD 40   // smem row stride (bf16 elems), pad 8 to kill conflicts
__global__ __launch_bounds__(256) void knn_wmma() {
    int b  = blockIdx.z;
    int n0 = blockIdx.y * 128;
    int m0 = blockIdx.x * 128;
    int bb = b << 11;

    __shared__ __nv_bfloat16 sA[128][SMLD];
    __shared__ __nv_bfloat16 sB[128][SMLD];

    int tid  = threadIdx.x;
    int warp = tid >> 5;
    int wm   = warp & 1;    // 2 warps along M (n)
    int wn   = warp >> 1;   // 4 warps along N (m)

    wmma::fragment<wmma::accumulator, 16, 16, 16, float> cf[4][2];
    #pragma unroll
    for (int i = 0; i < 4; i++)
        #pragma unroll
        for (int j = 0; j < 2; j++) wmma::fill_fragment(cf[i][j], 0.0f);

    // 18 chunks of BK=32: sections (A,B) = (hi,hi) | (hi,lo) | (lo,hi)
    for (int t = 0; t < 18; t++) {
        int sec = t / 6;
        int dof = (t - sec * 6) * 32;
        const __nv_bfloat16* Aarr = (sec < 2) ? g_hi : g_lo;
        const __nv_bfloat16* Barr = (sec == 1) ? g_lo : g_hi;
        #pragma unroll
        for (int r = 0; r < 2; r++) {
            int idx = tid + r * 256;        // 512 int4 slots per tile
            int row = idx >> 2;
            int c8  = (idx & 3) * 8;
            *(int4*)&sA[row][c8] = *(const int4*)&Aarr[(size_t)(bb + n0 + row) * DTOT + dof + c8];
            *(int4*)&sB[row][c8] = *(const int4*)&Barr[(size_t)(bb + m0 + row) * DTOT + dof + c8];
        }
        __syncthreads();
        #pragma unroll
        for (int kk = 0; kk < 32; kk += 16) {
            wmma::fragment<wmma::matrix_a, 16, 16, 16, __nv_bfloat16, wmma::row_major> af[4];
            wmma::fragment<wmma::matrix_b, 16, 16, 16, __nv_bfloat16, wmma::col_major> bfr[2];
            #pragma unroll
            for (int i = 0; i < 4; i++)
                wmma::load_matrix_sync(af[i], &sA[wm * 64 + i * 16][kk], SMLD);
            #pragma unroll
            for (int j = 0; j < 2; j++)
                wmma::load_matrix_sync(bfr[j], &sB[wn * 32 + j * 16][kk], SMLD);
            #pragma unroll
            for (int i = 0; i < 4; i++)
                #pragma unroll
                for (int j = 0; j < 2; j++)
                    wmma::mma_sync(cf[i][j], af[i], bfr[j], cf[i][j]);
        }
        __syncthreads();
    }

    // augmented tail k16: A=[1,1,0..], B=[hx_m,lx_m,0..]  -> adds -0.5*xx_m
    {
        const __nv_bfloat16 one = __float2bfloat16(1.0f);
        const __nv_bfloat16 zero = __float2bfloat16(0.0f);
        if (tid < 128) {
            int row = tid;
            sA[row][0] = one; sA[row][1] = one;
            #pragma unroll
            for (int c = 2; c < 16; c++) sA[row][c] = zero;
        } else {
            int row = tid - 128;
            sB[row][0] = g_hx[bb + m0 + row];
            sB[row][1] = g_lx[bb + m0 + row];
            #pragma unroll
            for (int c = 2; c < 16; c++) sB[row][c] = zero;
        }
        __syncthreads();
        wmma::fragment<wmma::matrix_a, 16, 16, 16, __nv_bfloat16, wmma::row_major> af[4];
        wmma::fragment<wmma::matrix_b, 16, 16, 16, __nv_bfloat16, wmma::col_major> bfr[2];
        #pragma unroll
        for (int i = 0; i < 4; i++)
            wmma::load_matrix_sync(af[i], &sA[wm * 64 + i * 16][0], SMLD);
        #pragma unroll
        for (int j = 0; j < 2; j++)
            wmma::load_matrix_sync(bfr[j], &sB[wn * 32 + j * 16][0], SMLD);
        #pragma unroll
        for (int i = 0; i < 4; i++)
            #pragma unroll
            for (int j = 0; j < 2; j++)
                wmma::mma_sync(cf[i][j], af[i], bfr[j], cf[i][j]);
    }

    // store raw scores
    #pragma unroll
    for (int i = 0; i < 4; i++)
        #pragma unroll
        for (int j = 0; j < 2; j++) {
            float* op = g_pdist + ((size_t)(bb + n0 + wm * 64 + i * 16)) * NPT
                        + m0 + wn * 32 + j * 16;
            wmma::store_matrix_sync(op, cf[i][j], NPT, wmma::mem_row_major);
        }
}

// ---------------- 3: approx top-TCAND per row (warp per row, float4 + skip) ----------------
__global__ void cand_kernel() {
    int gwarp = (blockIdx.x * blockDim.x + threadIdx.x) >> 5;   // row id [0,16384)
    int lane  = threadIdx.x & 31;
    int wl    = threadIdx.x >> 5;

    __shared__ float sv[8][32 * TCAND];
    __shared__ int   si[8][32 * TCAND];

    const float4* row4 = (const float4*)(g_pdist + (size_t)gwarp * NPT);
    float tv[TCAND]; int ti[TCAND];
    #pragma unroll
    for (int j = 0; j < TCAND; j++) { tv[j] = -INFINITY; ti[j] = 0; }

    #pragma unroll 4
    for (int i = 0; i < NPT / 128; i++) {
        int q = i * 32 + lane;              // float4 slot
        float4 v4 = row4[q];
        float mx = fmaxf(fmaxf(v4.x, v4.y), fmaxf(v4.z, v4.w));
        if (mx > tv[TCAND - 1]) {
            float vals[4] = {v4.x, v4.y, v4.z, v4.w};
            #pragma unroll
            for (int c = 0; c < 4; c++) {
                float vv = vals[c];
                if (vv > tv[TCAND - 1]) {
                    float cv = vv; int ci = q * 4 + c;
                    #pragma unroll
                    for (int j = 0; j < TCAND; j++) {
                        if (cv > tv[j]) {
                            float tt = tv[j]; tv[j] = cv; cv = tt;
                            int qq = ti[j]; ti[j] = ci; ci = qq;
                        }
                    }
                }
            }
        }
    }
    #pragma unroll
    for (int j = 0; j < TCAND; j++) {
        sv[wl][lane * TCAND + j] = tv[j];
        si[wl][lane * TCAND + j] = ti[j];
    }
    __syncwarp();

    int* out = g_cand + (size_t)gwarp * TCAND;
    for (int r = 0; r < TCAND; r++) {
        float bv = -INFINITY; int bs = 0;
        #pragma unroll
        for (int t = 0; t < TCAND; t++) {
            int s = lane * TCAND + t;
            float vv = sv[wl][s];
            if (vv > bv) { bv = vv; bs = s; }
        }
        #pragma unroll
        for (int off = 16; off; off >>= 1) {
            float ov = __shfl_down_sync(0xffffffff, bv, off);
            int   os = __shfl_down_sync(0xffffffff, bs, off);
            if (ov > bv) { bv = ov; bs = os; }
        }
        bs = __shfl_sync(0xffffffff, bs, 0);
        if (lane == 0) { out[r] = si[wl][bs]; sv[wl][bs] = -INFINITY; }
        __syncwarp();
    }
}

// ---------------- 4: exact fp64 refine of candidates -> final top-KNN ----------------
__global__ __launch_bounds__(256) void refine_kernel() {
    int row  = (blockIdx.x * blockDim.x + threadIdx.x) >> 5;  // [0,16384)
    int lane = threadIdx.x & 31;
    int wl   = threadIdx.x >> 5;
    int b    = row >> 11;

    __shared__ float s_val[8][TCAND];
    __shared__ int   s_id[8][TCAND];

    float xn[6];
    #pragma unroll
    for (int u = 0; u < 6; u++) xn[u] = g_xt[(size_t)row * DTOT + lane + 32 * u];
    float xxn = (float)g_xx64[row];

    for (int j = 0; j < TCAND; j++) {
        int m = g_cand[(size_t)row * TCAND + j];
        const float* xm = g_xt + ((size_t)(b << 11) + m) * DTOT;
        double acc = 0.0;
        #pragma unroll
        for (int u = 0; u < 6; u++) acc += (double)xn[u] * (double)xm[lane + 32 * u];
        #pragma unroll
        for (int off = 16; off; off >>= 1) acc += __shfl_down_sync(0xffffffff, acc, off);
        if (lane == 0) {
            // emulate reference's fp32 expression structure for tie alignment:
            float innerf = (float)acc;
            float pf = 2.0f * innerf;
            pf = pf - xxn;
            pf = pf - (float)g_xx64[(size_t)(b << 11) + m];
            s_val[wl][j] = pf;
            s_id[wl][j]  = m;
        }
    }
    __syncwarp();

    if (lane == 0) {
        int* out = g_idx + (size_t)row * KNN;
        for (int r = 0; r < KNN; r++) {
            float bv = -INFINITY; int bi = 0x7fffffff; int bs = 0;
            #pragma unroll
            for (int t = 0; t < TCAND; t++) {
                float v = s_val[wl][t]; int id = s_id[wl][t];
                if (v > bv || (v == bv && id < bi)) { bv = v; bi = id; bs = t; }
            }
            out[r] = bi;
            s_val[wl][bs] = -INFINITY;
        }
    }
}

// ---------------- 5: y_feat / y_dir  [bm][od] ----------------
__global__ void feat_kernel(const float* __restrict__ x,
                            const float* __restrict__ Wf,
                            const float* __restrict__ Wd) {
    __shared__ float wfs[64][64];   // [c][o]
    __shared__ float wds[64][64];
    __shared__ float xs[DTOT][16];

    int b = blockIdx.y;
    int n0 = blockIdx.x * 16;
    int tid = threadIdx.x;          // 192

    for (int i = tid; i < 4096; i += 192) {
        int o = i >> 6, c = i & 63;
        wfs[c][o] = Wf[i];
        wds[c][o] = Wd[i];
    }
    const float* X = x + (size_t)b * DTOT * NPT;
    for (int i = tid; i < DTOT * 16; i += 192) {
        int c3 = i >> 4, n = i & 15;
        xs[c3][n] = X[(size_t)c3 * NPT + n0 + n];
    }
    __syncthreads();

    int o = tid / 3;
    int d = tid - 3 * o;

    float af[16], ad_[16];
    #pragma unroll
    for (int n = 0; n < 16; n++) { af[n] = 0.f; ad_[n] = 0.f; }

    for (int c = 0; c < 64; c++) {
        float wf = wfs[c][o], wd = wds[c][o];
        #pragma unroll
        for (int n = 0; n < 16; n++) {
            float xv = xs[c * 3 + d][n];
            af[n]  = fmaf(wf, xv, af[n]);
            ad_[n] = fmaf(wd, xv, ad_[n]);
        }
    }
    #pragma unroll
    for (int n = 0; n < 16; n++) {
        size_t base = ((size_t)b * NPT + n0 + n) * DTOT + tid;
        g_yf[base] = af[n];
        g_yd[base] = ad_[n];
    }
}

// ---------------- 6: per-point norm / f·d / |d|^2 ----------------
__global__ void pstat_kernel() {
    int t = blockIdx.x * blockDim.x + threadIdx.x;  // 16384*64
    int bm = t >> 6;
    int o  = t & 63;
    const float* f = g_yf + (size_t)bm * DTOT + o * 3;
    const float* g = g_yd + (size_t)bm * DTOT + o * 3;
    float f0 = f[0], f1 = f[1], f2 = f[2];
    float g0 = g[0], g1 = g[1], g2 = g[2];
    g_nrm[t] = sqrtf(f0 * f0 + f1 * f1 + f2 * f2);
    g_dfd[t] = f0 * g0 + f1 * g1 + f2 * g2;
    g_dsq[t] = g0 * g0 + g1 * g1 + g2 * g2;
}

// ---------------- 7: neighbor counts ----------------
__global__ void zero_cnt() {
    int t = blockIdx.x * blockDim.x + threadIdx.x;
    if (t < NPAIR) g_cnt[t] = 0;
}
__global__ void count_kernel() {
    int t = blockIdx.x * blockDim.x + threadIdx.x;  // NEDGE = 180224
    if (t < NEDGE) {
        int b = t / (NPT * KNN);
        atomicAdd(&g_cnt[b * NPT + g_idx[t]], 1);
    }
}

// ---------------- 8: BN stats (count-weighted, exact) ----------------
__global__ void bnstat_kernel(const float* __restrict__ gamma, const float* __restrict__ beta) {
    int o = blockIdx.x;
    int tid = threadIdx.x;  // 256
    double s1 = 0.0, s2 = 0.0;
    for (int bm = tid; bm < NPAIR; bm += 256) {
        float v = g_nrm[(size_t)bm * COUT + o];
        double c = (double)g_cnt[bm];
        s1 += c * v;
        s2 += c * (double)v * (double)v;
    }
    __shared__ double r1[256], r2[256];
    r1[tid] = s1; r2[tid] = s2;
    __syncthreads();
    for (int s = 128; s; s >>= 1) {
        if (tid < s) { r1[tid] += r1[tid + s]; r2[tid] += r2[tid + s]; }
        __syncthreads();
    }
    if (tid == 0) {
        const double cnt = (double)NEDGE;
        double mean = r1[0] / cnt;
        double var  = r2[0] / cnt - mean * mean;
        double a = (double)gamma[o] / sqrt(var + (double)BN_EPS);
        g_chA[o] = (float)a;
        g_chB[o] = (float)((double)beta[o] - mean * a);
    }
}

// ---------------- 9: per-point output vectors v ----------------
__global__ void v_kernel() {
    int bm = blockIdx.x;
    int od = threadIdx.x;       // 192
    int o = od / 3;
    size_t t = (size_t)bm * DTOT + od;
    size_t s = (size_t)bm * COUT + o;
    float n    = g_nrm[s];
    float scale = g_chA[o] + g_chB[o] / n;     // norm_bn / norm
    float dot  = scale * g_dfd[s];
    float pv   = scale * g_yf[t];
    float outv = pv;
    if (dot < 0.f) outv = pv - dot / (g_dsq[s] + VN_EPS) * g_yd[t];
    g_v[t] = outv;
}

// ---------------- 10: gather-mean to output ----------------
__global__ void gather_kernel(float* __restrict__ out) {
    __shared__ int sidx[16 * KNN];
    int b  = blockIdx.y;
    int n0 = blockIdx.x * 16;
    int tid = threadIdx.x;      // 192
    if (tid < 16 * KNN) sidx[tid] = g_idx[((size_t)b * NPT + n0) * KNN + tid];
    __syncthreads();

    const float* vb = g_v + (size_t)b * NPT * DTOT;
    float res[16];
    #pragma unroll
    for (int n = 0; n < 16; n++) {
        float acc = 0.f;
        #pragma unroll
        for (int k = 0; k < KNN; k++) {
            int m = sidx[n * KNN + k];
            acc += vb[(size_t)m * DTOT + tid];
        }
        res[n] = acc * (1.0f / (float)KNN);
    }
    float* ob = out + ((size_t)b * DTOT + tid) * NPT + n0;
    *(float4*)(ob)      = make_float4(res[0],  res[1],  res[2],  res[3]);
    *(float4*)(ob + 4)  = make_float4(res[4],  res[5],  res[6],  res[7]);
    *(float4*)(ob + 8)  = make_float4(res[8],  res[9],  res[10], res[11]);
    *(float4*)(ob + 12) = make_float4(res[12], res[13], res[14], res[15]);
}

// ---------------- launch ----------------
extern "C" void kernel_launch(void* const* d_in, const int* in_sizes, int n_in,
                              void* d_out, int out_size) {
    const float* x     = (const float*)d_in[0];
    const float* Wf    = (const float*)d_in[1];
    const float* Wd    = (const float*)d_in[2];
    const float* gamma = (const float*)d_in[3];
    const float* beta  = (const float*)d_in[4];
    float* out = (float*)d_out;

    xt_kernel<<<dim3(NPT / 32, DTOT / 32, BATCH), dim3(32, 32)>>>(x);
    xx64_kernel<<<NPAIR / 256, 256>>>();
    knn_wmma<<<dim3(NPT / 128, NPT / 128, BATCH), 256>>>();
    cand_kernel<<<NPAIR / 8, 256>>>();
    refine_kernel<<<NPAIR / 8, 256>>>();
    feat_kernel<<<dim3(NPT / 16, BATCH), 192>>>(x, Wf, Wd);
    pstat_kernel<<<(NPAIR * COUT) / 256, 256>>>();
    zero_cnt<<<NPAIR / 256, 256>>>();
    count_kernel<<<(NEDGE + 255) / 256, 256>>>();
    bnstat_kernel<<<COUT, 256>>>(gamma, beta);
    v_kernel<<<NPAIR, DTOT>>>();
    gather_kernel<<<dim3(NPT / 16, BATCH), DTOT>>>(out);
}

// round 5
// speedup vs baseline: 2.2736x; 1.3170x over previous
#include <cuda_runtime.h>
#include <cuda_bf16.h>
#include <mma.h>
#include <math.h>

using namespace nvcuda;

// Problem constants (fixed by the bench)
#define BATCH 8
#define CIN   64
#define COUT  64
#define NPT   2048
#define DTOT  192           // 3*Cin feature dim for kNN
#define KNN   11            // k+1
#define NPAIR (BATCH*NPT)   // 16384 points total
#define NEDGE (BATCH*NPT*KNN)
#define TCAND 16            // candidates kept per row before exact refine
#define CCAP  320           // per-row candidate collection capacity

#define VN_EPS 1e-6f
#define BN_EPS 1e-5f

// ---------------- scratch (device globals; no cudaMalloc allowed) ----------------
__device__ float          g_pdist[(size_t)BATCH * NPT * NPT];   // 134 MB (rank scores)
__device__ float          g_rtm[(size_t)NPAIR * 16];            // per-row per-128-tile max
__device__ float          g_xt[(size_t)NPAIR * DTOT];           // transposed x: [bm][d]
__device__ __nv_bfloat16  g_hi[(size_t)NPAIR * DTOT];           // bf16 of xt
__device__ double         g_xx64[NPAIR];
__device__ __nv_bfloat16  g_hx[NPAIR];                          // bf16 hi of -0.5*xx
__device__ __nv_bfloat16  g_lx[NPAIR];                          // bf16 lo of -0.5*xx
__device__ int            g_cand[(size_t)NPAIR * TCAND];
__device__ int            g_idx[NEDGE];
__device__ float          g_yf[(size_t)NPAIR * DTOT];           // [bm][o*3+d]
__device__ float          g_yd[(size_t)NPAIR * DTOT];
__device__ float          g_nrm[(size_t)NPAIR * COUT];          // [bm][o]
__device__ float          g_dfd[(size_t)NPAIR * COUT];
__device__ float          g_dsq[(size_t)NPAIR * COUT];
__device__ float          g_v[(size_t)NPAIR * DTOT];            // per-point output vectors
__device__ int            g_cnt[NPAIR];
__device__ float          g_chA[COUT];
__device__ float          g_chB[COUT];

// ---------------- 0: transpose x -> g_xt [bm][d]; emit bf16 ----------------
__global__ void xt_kernel(const float* __restrict__ x) {
    __shared__ float t[32][33];
    int b  = blockIdx.z;
    int d0 = blockIdx.y * 32;
    int n0 = blockIdx.x * 32;
    const float* X = x + (size_t)b * DTOT * NPT;
    t[threadIdx.y][threadIdx.x] = X[(size_t)(d0 + threadIdx.y) * NPT + n0 + threadIdx.x];
    __syncthreads();
    float v = t[threadIdx.x][threadIdx.y];
    size_t o = ((size_t)(b << 11) + n0 + threadIdx.y) * DTOT + d0 + threadIdx.x;
    g_xt[o] = v;
    g_hi[o] = __float2bfloat16(v);
}

// ---------------- 1: xx in fp64 (exact) + bf16 hi/lo of -0.5*xx; zero counts ----------------
__global__ void xx64_kernel() {
    int p = blockIdx.x * blockDim.x + threadIdx.x;      // 16384 points
    const float* r = g_xt + (size_t)p * DTOT;
    double s = 0.0;
    #pragma unroll 8
    for (int d = 0; d < DTOT; d++) { double v = (double)r[d]; s += v * v; }
    g_xx64[p] = s;
    float m05 = (float)(-0.5 * s);
    __nv_bfloat16 hx = __float2bfloat16(m05);
    g_hx[p] = hx;
    g_lx[p] = __float2bfloat16(m05 - __bfloat162float(hx));
    g_cnt[p] = 0;
}

// ---------------- 2: tensor-core rank-score GEMM + per-row tile max ----------------
// score[n][m] = x_n.x_m - 0.5*xx_m   (per-row-monotone transform of pdist)
#define SMLD 40   // smem row stride (bf16 elems), pad 8 to kill conflicts
__global__ __launch_bounds__(256) void knn_wmma() {
    int b  = blockIdx.z;
    int n0 = blockIdx.y * 128;
    int m0 = blockIdx.x * 128;
    int bb = b << 11;

    __shared__ __nv_bfloat16 sA[128][SMLD];
    __shared__ __nv_bfloat16 sB[128][SMLD];

    int tid  = threadIdx.x;
    int warp = tid >> 5;
    int wm   = warp & 1;    // 2 warps along rows (n)
    int wn   = warp >> 1;   // 4 warps along cols (m)

    wmma::fragment<wmma::accumulator, 16, 16, 16, float> cf[4][2];
    #pragma unroll
    for (int i = 0; i < 4; i++)
        #pragma unroll
        for (int j = 0; j < 2; j++) wmma::fill_fragment(cf[i][j], 0.0f);

    // 6 chunks of BK=32 over K=192, single bf16 term
    for (int t = 0; t < 6; t++) {
        int dof = t * 32;
        #pragma unroll
        for (int r = 0; r < 2; r++) {
            int idx = tid + r * 256;        // 512 int4 slots per tile
            int row = idx >> 2;
            int c8  = (idx & 3) * 8;
            *(int4*)&sA[row][c8] = *(const int4*)&g_hi[(size_t)(bb + n0 + row) * DTOT + dof + c8];
            *(int4*)&sB[row][c8] = *(const int4*)&g_hi[(size_t)(bb + m0 + row) * DTOT + dof + c8];
        }
        __syncthreads();
        #pragma unroll
        for (int kk = 0; kk < 32; kk += 16) {
            wmma::fragment<wmma::matrix_a, 16, 16, 16, __nv_bfloat16, wmma::row_major> af[4];
            wmma::fragment<wmma::matrix_b, 16, 16, 16, __nv_bfloat16, wmma::col_major> bfr[2];
            #pragma unroll
            for (int i = 0; i < 4; i++)
                wmma::load_matrix_sync(af[i], &sA[wm * 64 + i * 16][kk], SMLD);
            #pragma unroll
            for (int j = 0; j < 2; j++)
                wmma::load_matrix_sync(bfr[j], &sB[wn * 32 + j * 16][kk], SMLD);
            #pragma unroll
            for (int i = 0; i < 4; i++)
                #pragma unroll
                for (int j = 0; j < 2; j++)
                    wmma::mma_sync(cf[i][j], af[i], bfr[j], cf[i][j]);
        }
        __syncthreads();
    }

    // augmented tail k16: A=[1,1,0..], B=[hx_m,lx_m,0..]  -> adds -0.5*xx_m
    {
        const __nv_bfloat16 one = __float2bfloat16(1.0f);
        const __nv_bfloat16 zero = __float2bfloat16(0.0f);
        if (tid < 128) {
            int row = tid;
            sA[row][0] = one; sA[row][1] = one;
            #pragma unroll
            for (int c = 2; c < 16; c++) sA[row][c] = zero;
        } else {
            int row = tid - 128;
            sB[row][0] = g_hx[bb + m0 + row];
            sB[row][1] = g_lx[bb + m0 + row];
            #pragma unroll
            for (int c = 2; c < 16; c++) sB[row][c] = zero;
        }
        __syncthreads();
        wmma::fragment<wmma::matrix_a, 16, 16, 16, __nv_bfloat16, wmma::row_major> af[4];
        wmma::fragment<wmma::matrix_b, 16, 16, 16, __nv_bfloat16, wmma::col_major> bfr[2];
        #pragma unroll
        for (int i = 0; i < 4; i++)
            wmma::load_matrix_sync(af[i], &sA[wm * 64 + i * 16][0], SMLD);
        #pragma unroll
        for (int j = 0; j < 2; j++)
            wmma::load_matrix_sync(bfr[j], &sB[wn * 32 + j * 16][0], SMLD);
        #pragma unroll
        for (int i = 0; i < 4; i++)
            #pragma unroll
            for (int j = 0; j < 2; j++)
                wmma::mma_sync(cf[i][j], af[i], bfr[j], cf[i][j]);
    }

    // store raw scores
    #pragma unroll
    for (int i = 0; i < 4; i++)
        #pragma unroll
        for (int j = 0; j < 2; j++) {
            float* op = g_pdist + ((size_t)(bb + n0 + wm * 64 + i * 16)) * NPT
                        + m0 + wn * 32 + j * 16;
            wmma::store_matrix_sync(op, cf[i][j], NPT, wmma::mem_row_major);
        }

    // per-row max of this 128x128 tile (reads back own stores; block-visible after sync)
    __syncthreads();
    {
        float* smax = (float*)&sA[0][0];          // reuse smem
        int row  = tid >> 1;
        int half = tid & 1;
        const float4* p = (const float4*)(g_pdist + (size_t)(bb + n0 + row) * NPT + m0 + half * 64);
        float mx = -INFINITY;
        #pragma unroll
        for (int j = 0; j < 16; j++) {
            float4 v = p[j];
            mx = fmaxf(mx, fmaxf(fmaxf(v.x, v.y), fmaxf(v.z, v.w)));
        }
        smax[row * 2 + half] = mx;
        __syncthreads();
        if (tid < 128)
            g_rtm[(size_t)(bb + n0 + tid) * 16 + blockIdx.x] = fmaxf(smax[tid * 2], smax[tid * 2 + 1]);
    }
}

// ---------------- 3: threshold-collect top-TCAND per row (warp per row) ----------------
__global__ __launch_bounds__(256) void cand_kernel() {
    int gwarp = (blockIdx.x * blockDim.x + threadIdx.x) >> 5;   // row id [0,16384)
    int lane  = threadIdx.x & 31;
    int wl    = threadIdx.x >> 5;

    __shared__ float s_v[8][CCAP];
    __shared__ int   s_i[8][CCAP];

    // tau = min of the 16 tile maxima  (guarantees >=16 elements >= tau)
    float tm = (lane < 16) ? g_rtm[(size_t)gwarp * 16 + lane] : INFINITY;
    #pragma unroll
    for (int off = 8; off; off >>= 1) tm = fminf(tm, __shfl_down_sync(0xffffffff, tm, off));
    float tau = __shfl_sync(0xffffffff, tm, 0);

    const float4* row4 = (const float4*)(g_pdist + (size_t)gwarp * NPT);
    int base = 0;
    #pragma unroll 2
    for (int i = 0; i < NPT / 128; i++) {
        int q = i * 32 + lane;
        float4 v = row4[q];
        float mx = fmaxf(fmaxf(v.x, v.y), fmaxf(v.z, v.w));
        unsigned any = __ballot_sync(0xffffffff, mx >= tau);
        if (any) {
            float vals[4] = {v.x, v.y, v.z, v.w};
            #pragma unroll
            for (int c = 0; c < 4; c++) {
                bool hit = vals[c] >= tau;
                unsigned m = __ballot_sync(0xffffffff, hit);
                if (m) {
                    if (hit) {
                        int pos = base + __popc(m & ((1u << lane) - 1));
                        if (pos < CCAP) { s_v[wl][pos] = vals[c]; s_i[wl][pos] = q * 4 + c; }
                    }
                    base += __popc(m);
                }
            }
        }
    }
    int cnt = min(base, CCAP);
    __syncwarp();

    // top-TCAND of collected (value desc, index asc)
    int* out = g_cand + (size_t)gwarp * TCAND;
    for (int r = 0; r < TCAND; r++) {
        float bv = -INFINITY; int bi = 0x7fffffff;
        for (int t = lane; t < cnt; t += 32) {
            float vv = s_v[wl][t]; int ii = s_i[wl][t];
            if (vv > bv || (vv == bv && ii < bi)) { bv = vv; bi = ii; }
        }
        #pragma unroll
        for (int off = 16; off; off >>= 1) {
            float ov = __shfl_down_sync(0xffffffff, bv, off);
            int   oi = __shfl_down_sync(0xffffffff, bi, off);
            if (ov > bv || (ov == bv && oi < bi)) { bv = ov; bi = oi; }
        }
        bv = __shfl_sync(0xffffffff, bv, 0);
        bi = __shfl_sync(0xffffffff, bi, 0);
        if (lane == 0) out[r] = bi;
        for (int t = lane; t < cnt; t += 32)
            if (s_i[wl][t] == bi) s_v[wl][t] = -INFINITY;
        __syncwarp();
    }
}

// ---------------- 4: exact fp64 refine of candidates -> final top-KNN ----------------
__global__ __launch_bounds__(256) void refine_kernel() {
    int row  = (blockIdx.x * blockDim.x + threadIdx.x) >> 5;  // [0,16384)
    int lane = threadIdx.x & 31;
    int wl   = threadIdx.x >> 5;
    int b    = row >> 11;

    __shared__ float s_val[8][TCAND];
    __shared__ int   s_id[8][TCAND];

    float xn[6];
    #pragma unroll
    for (int u = 0; u < 6; u++) xn[u] = g_xt[(size_t)row * DTOT + lane + 32 * u];
    float xxn = (float)g_xx64[row];

    for (int j = 0; j < TCAND; j++) {
        int m = g_cand[(size_t)row * TCAND + j];
        const float* xm = g_xt + ((size_t)(b << 11) + m) * DTOT;
        double acc = 0.0;
        #pragma unroll
        for (int u = 0; u < 6; u++) acc += (double)xn[u] * (double)xm[lane + 32 * u];
        #pragma unroll
        for (int off = 16; off; off >>= 1) acc += __shfl_down_sync(0xffffffff, acc, off);
        if (lane == 0) {
            // emulate reference's fp32 expression structure for tie alignment:
            float innerf = (float)acc;
            float pf = 2.0f * innerf;
            pf = pf - xxn;
            pf = pf - (float)g_xx64[(size_t)(b << 11) + m];
            s_val[wl][j] = pf;
            s_id[wl][j]  = m;
        }
    }
    __syncwarp();

    if (lane == 0) {
        int* out = g_idx + (size_t)row * KNN;
        for (int r = 0; r < KNN; r++) {
            float bv = -INFINITY; int bi = 0x7fffffff; int bs = 0;
            #pragma unroll
            for (int t = 0; t < TCAND; t++) {
                float v = s_val[wl][t]; int id = s_id[wl][t];
                if (v > bv || (v == bv && id < bi)) { bv = v; bi = id; bs = t; }
            }
            out[r] = bi;
            s_val[wl][bs] = -INFINITY;
        }
    }
}

// ---------------- 5: y_feat / y_dir  [bm][od] ----------------
__global__ void feat_kernel(const float* __restrict__ x,
                            const float* __restrict__ Wf,
                            const float* __restrict__ Wd) {
    __shared__ float wfs[64][64];   // [c][o]
    __shared__ float wds[64][64];
    __shared__ float xs[DTOT][16];

    int b = blockIdx.y;
    int n0 = blockIdx.x * 16;
    int tid = threadIdx.x;          // 192

    for (int i = tid; i < 4096; i += 192) {
        int o = i >> 6, c = i & 63;
        wfs[c][o] = Wf[i];
        wds[c][o] = Wd[i];
    }
    const float* X = x + (size_t)b * DTOT * NPT;
    for (int i = tid; i < DTOT * 16; i += 192) {
        int c3 = i >> 4, n = i & 15;
        xs[c3][n] = X[(size_t)c3 * NPT + n0 + n];
    }
    __syncthreads();

    int o = tid / 3;
    int d = tid - 3 * o;

    float af[16], ad_[16];
    #pragma unroll
    for (int n = 0; n < 16; n++) { af[n] = 0.f; ad_[n] = 0.f; }

    for (int c = 0; c < 64; c++) {
        float wf = wfs[c][o], wd = wds[c][o];
        #pragma unroll
        for (int n = 0; n < 16; n++) {
            float xv = xs[c * 3 + d][n];
            af[n]  = fmaf(wf, xv, af[n]);
            ad_[n] = fmaf(wd, xv, ad_[n]);
        }
    }
    #pragma unroll
    for (int n = 0; n < 16; n++) {
        size_t base = ((size_t)b * NPT + n0 + n) * DTOT + tid;
        g_yf[base] = af[n];
        g_yd[base] = ad_[n];
    }
}

// ---------------- 6: per-point norm / f·d / |d|^2 ----------------
__global__ void pstat_kernel() {
    int t = blockIdx.x * blockDim.x + threadIdx.x;  // 16384*64
    int bm = t >> 6;
    int o  = t & 63;
    const float* f = g_yf + (size_t)bm * DTOT + o * 3;
    const float* g = g_yd + (size_t)bm * DTOT + o * 3;
    float f0 = f[0], f1 = f[1], f2 = f[2];
    float g0 = g[0], g1 = g[1], g2 = g[2];
    g_nrm[t] = sqrtf(f0 * f0 + f1 * f1 + f2 * f2);
    g_dfd[t] = f0 * g0 + f1 * g1 + f2 * g2;
    g_dsq[t] = g0 * g0 + g1 * g1 + g2 * g2;
}

// ---------------- 7: neighbor counts ----------------
__global__ void count_kernel() {
    int t = blockIdx.x * blockDim.x + threadIdx.x;  // NEDGE = 180224
    if (t < NEDGE) {
        int b = t / (NPT * KNN);
        atomicAdd(&g_cnt[b * NPT + g_idx[t]], 1);
    }
}

// ---------------- 8: BN stats (count-weighted, exact) ----------------
__global__ void bnstat_kernel(const float* __restrict__ gamma, const float* __restrict__ beta) {
    int o = blockIdx.x;
    int tid = threadIdx.x;  // 256
    double s1 = 0.0, s2 = 0.0;
    for (int bm = tid; bm < NPAIR; bm += 256) {
        float v = g_nrm[(size_t)bm * COUT + o];
        double c = (double)g_cnt[bm];
        s1 += c * v;
        s2 += c * (double)v * (double)v;
    }
    __shared__ double r1[256], r2[256];
    r1[tid] = s1; r2[tid] = s2;
    __syncthreads();
    for (int s = 128; s; s >>= 1) {
        if (tid < s) { r1[tid] += r1[tid + s]; r2[tid] += r2[tid + s]; }
        __syncthreads();
    }
    if (tid == 0) {
        const double cnt = (double)NEDGE;
        double mean = r1[0] / cnt;
        double var  = r2[0] / cnt - mean * mean;
        double a = (double)gamma[o] / sqrt(var + (double)BN_EPS);
        g_chA[o] = (float)a;
        g_chB[o] = (float)((double)beta[o] - mean * a);
    }
}

// ---------------- 9: per-point output vectors v ----------------
__global__ void v_kernel() {
    int bm = blockIdx.x;
    int od = threadIdx.x;       // 192
    int o = od / 3;
    size_t t = (size_t)bm * DTOT + od;
    size_t s = (size_t)bm * COUT + o;
    float n    = g_nrm[s];
    float scale = g_chA[o] + g_chB[o] / n;     // norm_bn / norm
    float dot  = scale * g_dfd[s];
    float pv   = scale * g_yf[t];
    float outv = pv;
    if (dot < 0.f) outv = pv - dot / (g_dsq[s] + VN_EPS) * g_yd[t];
    g_v[t] = outv;
}

// ---------------- 10: gather-mean to output ----------------
__global__ void gather_kernel(float* __restrict__ out) {
    __shared__ int sidx[16 * KNN];
    int b  = blockIdx.y;
    int n0 = blockIdx.x * 16;
    int tid = threadIdx.x;      // 192
    if (tid < 16 * KNN) sidx[tid] = g_idx[((size_t)b * NPT + n0) * KNN + tid];
    __syncthreads();

    const float* vb = g_v + (size_t)b * NPT * DTOT;
    float res[16];
    #pragma unroll
    for (int n = 0; n < 16; n++) {
        float acc = 0.f;
        #pragma unroll
        for (int k = 0; k < KNN; k++) {
            int m = sidx[n * KNN + k];
            acc += vb[(size_t)m * DTOT + tid];
        }
        res[n] = acc * (1.0f / (float)KNN);
    }
    float* ob = out + ((size_t)b * DTOT + tid) * NPT + n0;
    *(float4*)(ob)      = make_float4(res[0],  res[1],  res[2],  res[3]);
    *(float4*)(ob + 4)  = make_float4(res[4],  res[5],  res[6],  res[7]);
    *(float4*)(ob + 8)  = make_float4(res[8],  res[9],  res[10], res[11]);
    *(float4*)(ob + 12) = make_float4(res[12], res[13], res[14], res[15]);
}

// ---------------- launch ----------------
extern "C" void kernel_launch(void* const* d_in, const int* in_sizes, int n_in,
                              void* d_out, int out_size) {
    const float* x     = (const float*)d_in[0];
    const float* Wf    = (const float*)d_in[1];
    const float* Wd    = (const float*)d_in[2];
    const float* gamma = (const float*)d_in[3];
    const float* beta  = (const float*)d_in[4];
    float* out = (float*)d_out;

    xt_kernel<<<dim3(NPT / 32, DTOT / 32, BATCH), dim3(32, 32)>>>(x);
    xx64_kernel<<<NPAIR / 256, 256>>>();
    knn_wmma<<<dim3(NPT / 128, NPT / 128, BATCH), 256>>>();
    cand_kernel<<<NPAIR / 8, 256>>>();
    refine_kernel<<<NPAIR / 8, 256>>>();
    feat_kernel<<<dim3(NPT / 16, BATCH), 192>>>(x, Wf, Wd);
    pstat_kernel<<<(NPAIR * COUT) / 256, 256>>>();
    count_kernel<<<(NEDGE + 255) / 256, 256>>>();
    bnstat_kernel<<<COUT, 256>>>(gamma, beta);
    v_kernel<<<NPAIR, DTOT>>>();
    gather_kernel<<<dim3(NPT / 16, BATCH), DTOT>>>(out);
}